// round 9
// baseline (speedup 1.0000x reference)
#include <cuda_runtime.h>
#include <math.h>

#define SRC_LEN 48
#define TGT_LEN 48
#define BATCH   64
#define HID     512
#define G4      2048
#define VOCAB   32000
#define DSTEPS  47
#define NROWS   3008
#define NROWS_PAD 3072
#define WPITCH  24           // Wsm pitch: banks distinct per 8-lane phase
#define HPITCH  68           // hs/gsm pitch

// ---------------- scratch (device globals; zero at module load) -------------
// NOTE: these symbols are referenced ONLY from device code. Passing them as
// kernel arguments from host code is UB (host shadow address) and was the
// cause of the 128 MiB device-memory rule violations in rounds 2/4/6.
__device__ float g_Ge[SRC_LEN * 4 * HID * BATCH];   // [t][g][j][b]
__device__ float g_Gd[DSTEPS  * 4 * HID * BATCH];   // [t][g][j][b]
__device__ float g_Hpp[2][HID * BATCH];             // h' [j][b], ping-pong
__device__ float g_Cst[HID * BATCH];                // c  [j][b], in-place
__device__ float g_Hall[HID * NROWS_PAD];           // Hall' [j][m]; pad cols stay 0
__device__ float g_rowsum[NROWS];
__device__ float g_rowtgt[NROWS];

__device__ __forceinline__ float sigmoidf_(float x) {
    return 1.0f / (1.0f + __expf(-x));
}

__device__ __forceinline__ unsigned smem_u32(const void* p) {
    return (unsigned)__cvta_generic_to_shared(p);
}
__device__ __forceinline__ void cp_async16(unsigned s, const void* g) {
    asm volatile("cp.async.cg.shared.global [%0], [%1], 16;" :: "r"(s), "l"(g));
}

// ---------------- init: zero h0, c, rowsum -----------------------------------
__global__ void init_kernel() {
    int i = blockIdx.x * blockDim.x + threadIdx.x;
    if (i < HID * BATCH) { g_Hpp[0][i] = 0.0f; g_Cst[i] = 0.0f; }
    if (i < NROWS) g_rowsum[i] = 0.0f;
}

// ---------------- embed + input-gate GEMM, 128x128 tile, 8x8 microtile ------
// C[m][n] = emb_z[tok[m]] . W[n] + b1[n] + b2[n], written transposed into
// Gout[t][g][j][b] with m = t*64+b, n = g*512+j. Gout selected IN DEVICE CODE.
__global__ __launch_bounds__(256) void embed_gemm128(
    const int*   __restrict__ toks,
    const float* __restrict__ emb,
    const float* __restrict__ W,
    const float* __restrict__ b1,
    const float* __restrict__ b2,
    int is_enc,
    int R)
{
    __shared__ float As[16][132];
    __shared__ float Bs[16][132];
    float* __restrict__ Gout = is_enc ? g_Ge : g_Gd;   // device-side resolve

    int m0 = blockIdx.y * 128;
    int n0 = blockIdx.x * 128;
    int tid = threadIdx.x;
    int tx = tid & 15;
    int ty = tid >> 4;
    float acc[8][8] = {};

    for (int k0 = 0; k0 < HID; k0 += 16) {
        #pragma unroll
        for (int l = 0; l < 2; l++) {
            int idx = tid + l * 256;
            int m   = idx >> 2;
            int kq  = idx & 3;
            int gm  = m0 + m;
            int tok = (gm < R) ? toks[gm] : 0;
            float4 a = make_float4(0.f, 0.f, 0.f, 0.f);
            if (tok != 0) a = *(const float4*)&emb[(size_t)tok * HID + k0 + kq * 4];
            As[kq*4+0][m] = a.x; As[kq*4+1][m] = a.y;
            As[kq*4+2][m] = a.z; As[kq*4+3][m] = a.w;
            float4 w = *(const float4*)&W[(size_t)(n0 + m) * HID + k0 + kq * 4];
            Bs[kq*4+0][m] = w.x; Bs[kq*4+1][m] = w.y;
            Bs[kq*4+2][m] = w.z; Bs[kq*4+3][m] = w.w;
        }
        __syncthreads();
        #pragma unroll
        for (int k = 0; k < 16; k++) {
            float4 a0 = *(const float4*)&As[k][ty * 4];
            float4 a1 = *(const float4*)&As[k][64 + ty * 4];
            float4 w0 = *(const float4*)&Bs[k][tx * 4];
            float4 w1 = *(const float4*)&Bs[k][64 + tx * 4];
            float ar[8] = {a0.x, a0.y, a0.z, a0.w, a1.x, a1.y, a1.z, a1.w};
            float wr[8] = {w0.x, w0.y, w0.z, w0.w, w1.x, w1.y, w1.z, w1.w};
            #pragma unroll
            for (int i = 0; i < 8; i++)
                #pragma unroll
                for (int j = 0; j < 8; j++)
                    acc[i][j] = fmaf(ar[i], wr[j], acc[i][j]);
        }
        __syncthreads();
    }

    #pragma unroll
    for (int i = 0; i < 8; i++) {
        int gm = m0 + (i < 4 ? ty * 4 + i : 64 + ty * 4 + (i - 4));
        if (gm >= R) continue;
        int t = gm >> 6;
        int b = gm & 63;
        #pragma unroll
        for (int j = 0; j < 8; j++) {
            int gn = n0 + (j < 4 ? tx * 4 + j : 64 + tx * 4 + (j - 4));
            float v = acc[i][j] + b1[gn] + b2[gn];
            int g  = gn >> 9;
            int jj = gn & 511;
            Gout[(size_t)((t * 4 + g) * 512 + jj) * 64 + b] = v;
        }
    }
}

// ---------------- one LSTM step (lean; no register staging) ------------------
// Grid 128 x 256 threads. Block owns j0=bid*4..+3 -> 16 gate rows (g*4+jj).
// W slice staged k-major in smem once per step; h chunks (128 k) arrive via
// cp.async into a 2-deep smem ring. GEMM map: s=tid&3 (4-way k-split),
// rq=(tid>>2)&3 (gate), bq=tid>>4 (batch quad). acc[4][4]=16 regs.
// Update map: bb=tid&63, ju=tid>>6. c is in-place global (one owner/elem).
__global__ __launch_bounds__(256) void lstm_step(
    const float* __restrict__ Whh,
    const int*   __restrict__ input_lines,
    int is_enc, int t, int p)
{
    extern __shared__ float sm[];
    float* Wsm = sm;                          // [512][WPITCH]
    float* hs  = sm + 512 * WPITCH;           // [2][128][HPITCH]
    float* gsm = hs + 2 * 128 * HPITCH;       // [16][HPITCH]

    int tid = threadIdx.x;
    int j0  = blockIdx.x * 4;
    int s   = tid & 3;
    int rq  = (tid >> 2) & 3;
    int bq  = tid >> 4;
    int bb  = tid & 63;
    int ju  = tid >> 6;

    const float* __restrict__ hin  = g_Hpp[p];
    float*       __restrict__ hout = g_Hpp[1 - p];
    const float* __restrict__ Gt =
        (is_enc ? g_Ge : g_Gd) + (size_t)t * 4 * HID * BATCH;

    unsigned hs_base = smem_u32(hs);

    // kick off h chunk 0 (k 0..127) via cp.async
    #pragma unroll
    for (int i = 0; i < 8; i++) {
        int sl = tid + i * 256;               // 2048 16B slots
        int k = sl >> 4, q = sl & 15;
        cp_async16(hs_base + (unsigned)(k * HPITCH + q * 4) * 4u,
                   hin + k * 64 + q * 4);
    }
    asm volatile("cp.async.commit_group;");

    // stage W slice k-major (16 rows x 512 k); lr = g*4 + jj
    #pragma unroll
    for (int i = 0; i < 8; i++) {
        int sl = tid + i * 256;
        int lr = sl & 15;
        int kq = sl >> 4;                     // 0..127 (float4 along k)
        int g = lr >> 2, jj = lr & 3;
        float4 w = *(const float4*)&Whh[(size_t)(g * HID + j0 + jj) * HID + kq * 4];
        float* d = &Wsm[(size_t)(kq * 4) * WPITCH + lr];
        d[0 * WPITCH] = w.x; d[1 * WPITCH] = w.y;
        d[2 * WPITCH] = w.z; d[3 * WPITCH] = w.w;
    }

    // update-path early loads (scoreboard-waited at consumption)
    float gpre0 = Gt[(size_t)(0 * HID + j0 + ju) * 64 + bb];
    float gpre1 = Gt[(size_t)(1 * HID + j0 + ju) * 64 + bb];
    float gpre2 = Gt[(size_t)(2 * HID + j0 + ju) * 64 + bb];
    float gpre3 = Gt[(size_t)(3 * HID + j0 + ju) * 64 + bb];
    float hold = hin[(j0 + ju) * 64 + bb];
    float cold = g_Cst[(j0 + ju) * 64 + bb];
    int tok = is_enc ? input_lines[t * 64 + bb] : 1;

    float acc[4][4] = {};

    asm volatile("cp.async.wait_group 0;");
    __syncthreads();

    #pragma unroll
    for (int ch = 0; ch < 4; ch++) {
        int buf = ch & 1;
        if (ch < 3) {
            #pragma unroll
            for (int i = 0; i < 8; i++) {
                int sl = tid + i * 256;
                int k = sl >> 4, q = sl & 15;
                cp_async16(hs_base + (unsigned)(((1 - buf) * 128 + k) * HPITCH + q * 4) * 4u,
                           hin + ((ch + 1) * 128 + k) * 64 + q * 4);
            }
            asm volatile("cp.async.commit_group;");
        }
        #pragma unroll
        for (int kk = 0; kk < 32; kk++) {
            int kl = kk * 4 + s;              // 0..127 within chunk
            float4 w  = *(const float4*)&Wsm[(size_t)(ch * 128 + kl) * WPITCH + rq * 4];
            float4 h4 = *(const float4*)&hs[(size_t)(buf * 128 + kl) * HPITCH + bq * 4];
            float wr[4] = {w.x, w.y, w.z, w.w};
            float hr[4] = {h4.x, h4.y, h4.z, h4.w};
            #pragma unroll
            for (int ri = 0; ri < 4; ri++)
                #pragma unroll
                for (int bi = 0; bi < 4; bi++)
                    acc[ri][bi] = fmaf(wr[ri], hr[bi], acc[ri][bi]);
        }
        if (ch < 3) asm volatile("cp.async.wait_group 0;");
        __syncthreads();
    }

    // reduce over the 4 k-split lanes (lane bits 0..1); each s-lane emits one row
    #pragma unroll
    for (int ri = 0; ri < 4; ri++) {
        #pragma unroll
        for (int bi = 0; bi < 4; bi++) {
            float v = acc[ri][bi];
            v += __shfl_xor_sync(0xffffffffu, v, 1);
            v += __shfl_xor_sync(0xffffffffu, v, 2);
            acc[ri][bi] = v;
        }
        if (s == ri)
            *(float4*)&gsm[(rq * 4 + ri) * HPITCH + bq * 4] =
                make_float4(acc[ri][0], acc[ri][1], acc[ri][2], acc[ri][3]);
    }
    __syncthreads();

    // fused cell update; gate rows g*4 + ju
    {
        float iv = gsm[(0  + ju) * HPITCH + bb] + gpre0;
        float fv = gsm[(4  + ju) * HPITCH + bb] + gpre1;
        float gv = gsm[(8  + ju) * HPITCH + bb] + gpre2;
        float ov = gsm[(12 + ju) * HPITCH + bb] + gpre3;
        float c2 = sigmoidf_(fv) * cold + sigmoidf_(iv) * tanhf(gv);
        float h2 = sigmoidf_(ov) * tanhf(c2);
        if (is_enc && tok == 0) { c2 = cold; h2 = hold; }
        g_Cst[(j0 + ju) * 64 + bb] = c2;
        hout[(j0 + ju) * 64 + bb] = h2;
        if (!is_enc)
            g_Hall[(size_t)(j0 + ju) * NROWS_PAD + t * 64 + bb] = h2;
    }
}

// ---------------- projection + fused log-softmax pieces ---------------------
// A = Hall' [k][m] (k-major), B = W_out rows; 128x128 tile, 8x8 microtile.
__global__ __launch_bounds__(256) void proj_loss_kernel(
    const float* __restrict__ W,
    const float* __restrict__ bout,
    const int*   __restrict__ targets)
{
    __shared__ float As[16][132];
    __shared__ float Bs[16][132];

    int m0 = blockIdx.y * 128;
    int n0 = blockIdx.x * 128;
    int tid = threadIdx.x;
    int tx = tid & 15;
    int ty = tid >> 4;
    float acc[8][8] = {};

    for (int k0 = 0; k0 < HID; k0 += 16) {
        #pragma unroll
        for (int l = 0; l < 2; l++) {
            int idx = tid + l * 256;
            {   // A: Hall'[k][m] already k-major -> direct copy
                int k  = idx >> 5;
                int mq = idx & 31;
                float4 a = *(const float4*)&g_Hall[(size_t)(k0 + k) * NROWS_PAD + m0 + mq * 4];
                *(float4*)&As[k][mq * 4] = a;
            }
            {   // B: gather W rows transposed
                int m  = idx >> 2;
                int kq = idx & 3;
                float4 w = *(const float4*)&W[(size_t)(n0 + m) * HID + k0 + kq * 4];
                Bs[kq*4+0][m] = w.x; Bs[kq*4+1][m] = w.y;
                Bs[kq*4+2][m] = w.z; Bs[kq*4+3][m] = w.w;
            }
        }
        __syncthreads();
        #pragma unroll
        for (int k = 0; k < 16; k++) {
            float4 a0 = *(const float4*)&As[k][ty * 4];
            float4 a1 = *(const float4*)&As[k][64 + ty * 4];
            float4 w0 = *(const float4*)&Bs[k][tx * 4];
            float4 w1 = *(const float4*)&Bs[k][64 + tx * 4];
            float ar[8] = {a0.x, a0.y, a0.z, a0.w, a1.x, a1.y, a1.z, a1.w};
            float wr[8] = {w0.x, w0.y, w0.z, w0.w, w1.x, w1.y, w1.z, w1.w};
            #pragma unroll
            for (int i = 0; i < 8; i++)
                #pragma unroll
                for (int j = 0; j < 8; j++)
                    acc[i][j] = fmaf(ar[i], wr[j], acc[i][j]);
        }
        __syncthreads();
    }

    int   gncol[8];
    float bj[8];
    #pragma unroll
    for (int j = 0; j < 8; j++) {
        gncol[j] = n0 + (j < 4 ? tx * 4 + j : 64 + tx * 4 + (j - 4));
        bj[j] = bout[gncol[j]];
    }
    #pragma unroll
    for (int i = 0; i < 8; i++) {
        int gm = m0 + (i < 4 ? ty * 4 + i : 64 + ty * 4 + (i - 4));
        bool valid = (gm < NROWS);
        int tgt = valid ? targets[gm + BATCH] : -1;
        float sum = 0.0f;
        #pragma unroll
        for (int j = 0; j < 8; j++) {
            float logit = acc[i][j] + bj[j];
            sum += __expf(logit);
            if (valid && gncol[j] == tgt) g_rowtgt[gm] = logit;
        }
        #pragma unroll
        for (int o = 8; o > 0; o >>= 1)
            sum += __shfl_xor_sync(0xffffffffu, sum, o, 16);
        if (valid && tx == 0) atomicAdd(&g_rowsum[gm], sum);
    }
}

// ---------------- final loss reduction ---------------------------------------
__global__ void loss_reduce_kernel(float* __restrict__ out)
{
    __shared__ float sbuf[256];
    int tid = threadIdx.x;
    float s = 0.0f;
    for (int r = tid; r < NROWS; r += 256)
        s += logf(g_rowsum[r]) - g_rowtgt[r];
    sbuf[tid] = s;
    __syncthreads();
    for (int o = 128; o > 0; o >>= 1) {
        if (tid < o) sbuf[tid] += sbuf[tid + o];
        __syncthreads();
    }
    if (tid == 0) out[0] = sbuf[0] / (float)BATCH;
}

// ---------------- launch -----------------------------------------------------
extern "C" void kernel_launch(void* const* d_in, const int* in_sizes, int n_in,
                              void* d_out, int out_size)
{
    (void)in_sizes; (void)n_in; (void)out_size;
    const int*   input_lines  = (const int*)  d_in[0];
    const int*   target_lines = (const int*)  d_in[1];
    const float* emb_in       = (const float*)d_in[2];
    const float* emb_tgt      = (const float*)d_in[3];
    const float* W_ih_e       = (const float*)d_in[4];
    const float* W_hh_e       = (const float*)d_in[5];
    const float* b_ih_e       = (const float*)d_in[6];
    const float* b_hh_e       = (const float*)d_in[7];
    const float* W_ih_d       = (const float*)d_in[8];
    const float* W_hh_d       = (const float*)d_in[9];
    const float* b_ih_d       = (const float*)d_in[10];
    const float* b_hh_d       = (const float*)d_in[11];
    const float* W_out        = (const float*)d_in[12];
    const float* b_out        = (const float*)d_in[13];
    float* out = (float*)d_out;

    const int SMEM_BYTES = (512 * WPITCH + 2 * 128 * HPITCH + 16 * HPITCH) * 4;
    cudaFuncSetAttribute(lstm_step,
                         cudaFuncAttributeMaxDynamicSharedMemorySize,
                         SMEM_BYTES);

    init_kernel<<<(HID * BATCH + 255) / 256, 256>>>();

    embed_gemm128<<<dim3(G4 / 128, 24), 256>>>(
        input_lines, emb_in, W_ih_e, b_ih_e, b_hh_e, 1, SRC_LEN * BATCH);
    embed_gemm128<<<dim3(G4 / 128, 24), 256>>>(
        target_lines, emb_tgt, W_ih_d, b_ih_d, b_hh_d, 0, DSTEPS * BATCH);

    int p = 0;
    for (int t = 0; t < SRC_LEN; t++) {
        lstm_step<<<HID / 4, 256, SMEM_BYTES>>>(W_hh_e, input_lines, 1, t, p);
        p ^= 1;
    }
    for (int t = 0; t < DSTEPS; t++) {
        lstm_step<<<HID / 4, 256, SMEM_BYTES>>>(W_hh_d, input_lines, 0, t, p);
        p ^= 1;
    }

    proj_loss_kernel<<<dim3(VOCAB / 128, NROWS_PAD / 128), 256>>>(
        W_out, b_out, target_lines);

    loss_reduce_kernel<<<1, 256>>>(out);
}

// round 10
// speedup vs baseline: 1.9670x; 1.9670x over previous
#include <cuda_runtime.h>
#include <cuda_bf16.h>
#include <math.h>

#define SRC_LEN 48
#define TGT_LEN 48
#define BATCH   64
#define HID     512
#define G4      2048
#define VOCAB   32000
#define DSTEPS  47
#define NROWS   3008
#define NROWS_PAD 3072
#define WPITCH  24
#define HPITCH  68

// ---------------- scratch (device globals; device-code access ONLY) ---------
__device__ float g_Ge[SRC_LEN * 4 * HID * BATCH];   // [t][g][j][b]
__device__ float g_Gd[DSTEPS  * 4 * HID * BATCH];   // [t][g][j][b]
__device__ float g_Hpp[2][HID * BATCH];             // h' [j][b], ping-pong
__device__ float g_Cst[HID * BATCH];                // c  [j][b]
__device__ float g_Hall[HID * NROWS_PAD];           // Hall' [k][m]; pad stays 0
__device__ __nv_bfloat16 g_Ab[NROWS_PAD * HID];     // Hall bf16 [m][k]
__device__ __nv_bfloat16 g_Wb[VOCAB * HID];         // W_out bf16 [n][k]
__device__ float g_rowsum[NROWS];
__device__ float g_rowtgt[NROWS];

__device__ __forceinline__ float sigmoidf_(float x) {
    return 1.0f / (1.0f + __expf(-x));
}
__device__ __forceinline__ unsigned smem_u32(const void* p) {
    return (unsigned)__cvta_generic_to_shared(p);
}
__device__ __forceinline__ void cp_async16(unsigned s, const void* g) {
    asm volatile("cp.async.cg.shared.global [%0], [%1], 16;" :: "r"(s), "l"(g));
}
__device__ __forceinline__ void ldsm_x4(unsigned& r0, unsigned& r1,
                                        unsigned& r2, unsigned& r3, unsigned a) {
    asm volatile("ldmatrix.sync.aligned.m8n8.x4.shared.b16 {%0,%1,%2,%3}, [%4];"
                 : "=r"(r0), "=r"(r1), "=r"(r2), "=r"(r3) : "r"(a));
}
__device__ __forceinline__ void mma16816(float* d, const unsigned* a,
                                         unsigned b0, unsigned b1) {
    asm volatile(
        "mma.sync.aligned.m16n8k16.row.col.f32.bf16.bf16.f32 "
        "{%0,%1,%2,%3}, {%4,%5,%6,%7}, {%8,%9}, {%0,%1,%2,%3};"
        : "+f"(d[0]), "+f"(d[1]), "+f"(d[2]), "+f"(d[3])
        : "r"(a[0]), "r"(a[1]), "r"(a[2]), "r"(a[3]), "r"(b0), "r"(b1));
}

// ---------------- init -------------------------------------------------------
__global__ void init_kernel() {
    int i = blockIdx.x * blockDim.x + threadIdx.x;
    if (i < HID * BATCH) { g_Hpp[0][i] = 0.0f; g_Cst[i] = 0.0f; }
    if (i < NROWS) g_rowsum[i] = 0.0f;
}

// ---------------- embed + input-gate GEMM (unchanged, measured-good) --------
__global__ __launch_bounds__(256) void embed_gemm128(
    const int*   __restrict__ toks,
    const float* __restrict__ emb,
    const float* __restrict__ W,
    const float* __restrict__ b1,
    const float* __restrict__ b2,
    int is_enc,
    int R)
{
    __shared__ float As[16][132];
    __shared__ float Bs[16][132];
    float* __restrict__ Gout = is_enc ? g_Ge : g_Gd;

    int m0 = blockIdx.y * 128;
    int n0 = blockIdx.x * 128;
    int tid = threadIdx.x;
    int tx = tid & 15;
    int ty = tid >> 4;
    float acc[8][8] = {};

    for (int k0 = 0; k0 < HID; k0 += 16) {
        #pragma unroll
        for (int l = 0; l < 2; l++) {
            int idx = tid + l * 256;
            int m   = idx >> 2;
            int kq  = idx & 3;
            int gm  = m0 + m;
            int tok = (gm < R) ? toks[gm] : 0;
            float4 a = make_float4(0.f, 0.f, 0.f, 0.f);
            if (tok != 0) a = *(const float4*)&emb[(size_t)tok * HID + k0 + kq * 4];
            As[kq*4+0][m] = a.x; As[kq*4+1][m] = a.y;
            As[kq*4+2][m] = a.z; As[kq*4+3][m] = a.w;
            float4 w = *(const float4*)&W[(size_t)(n0 + m) * HID + k0 + kq * 4];
            Bs[kq*4+0][m] = w.x; Bs[kq*4+1][m] = w.y;
            Bs[kq*4+2][m] = w.z; Bs[kq*4+3][m] = w.w;
        }
        __syncthreads();
        #pragma unroll
        for (int k = 0; k < 16; k++) {
            float4 a0 = *(const float4*)&As[k][ty * 4];
            float4 a1 = *(const float4*)&As[k][64 + ty * 4];
            float4 w0 = *(const float4*)&Bs[k][tx * 4];
            float4 w1 = *(const float4*)&Bs[k][64 + tx * 4];
            float ar[8] = {a0.x, a0.y, a0.z, a0.w, a1.x, a1.y, a1.z, a1.w};
            float wr[8] = {w0.x, w0.y, w0.z, w0.w, w1.x, w1.y, w1.z, w1.w};
            #pragma unroll
            for (int i = 0; i < 8; i++)
                #pragma unroll
                for (int j = 0; j < 8; j++)
                    acc[i][j] = fmaf(ar[i], wr[j], acc[i][j]);
        }
        __syncthreads();
    }

    #pragma unroll
    for (int i = 0; i < 8; i++) {
        int gm = m0 + (i < 4 ? ty * 4 + i : 64 + ty * 4 + (i - 4));
        if (gm >= R) continue;
        int t = gm >> 6;
        int b = gm & 63;
        #pragma unroll
        for (int j = 0; j < 8; j++) {
            int gn = n0 + (j < 4 ? tx * 4 + j : 64 + tx * 4 + (j - 4));
            float v = acc[i][j] + b1[gn] + b2[gn];
            int g  = gn >> 9;
            int jj = gn & 511;
            Gout[(size_t)((t * 4 + g) * 512 + jj) * 64 + b] = v;
        }
    }
}

// ---------------- one LSTM step (unchanged, measured-good) -------------------
__global__ __launch_bounds__(256) void lstm_step(
    const float* __restrict__ Whh,
    const int*   __restrict__ input_lines,
    int is_enc, int t, int p)
{
    extern __shared__ float sm[];
    float* Wsm = sm;                          // [512][WPITCH]
    float* hs  = sm + 512 * WPITCH;           // [2][128][HPITCH]
    float* gsm = hs + 2 * 128 * HPITCH;       // [16][HPITCH]

    int tid = threadIdx.x;
    int j0  = blockIdx.x * 4;
    int s   = tid & 3;
    int rq  = (tid >> 2) & 3;
    int bq  = tid >> 4;
    int bb  = tid & 63;
    int ju  = tid >> 6;

    const float* __restrict__ hin  = g_Hpp[p];
    float*       __restrict__ hout = g_Hpp[1 - p];
    const float* __restrict__ Gt =
        (is_enc ? g_Ge : g_Gd) + (size_t)t * 4 * HID * BATCH;

    unsigned hs_base = smem_u32(hs);

    #pragma unroll
    for (int i = 0; i < 8; i++) {
        int sl = tid + i * 256;
        int k = sl >> 4, q = sl & 15;
        cp_async16(hs_base + (unsigned)(k * HPITCH + q * 4) * 4u,
                   hin + k * 64 + q * 4);
    }
    asm volatile("cp.async.commit_group;");

    #pragma unroll
    for (int i = 0; i < 8; i++) {
        int sl = tid + i * 256;
        int lr = sl & 15;
        int kq = sl >> 4;
        int g = lr >> 2, jj = lr & 3;
        float4 w = *(const float4*)&Whh[(size_t)(g * HID + j0 + jj) * HID + kq * 4];
        float* d = &Wsm[(size_t)(kq * 4) * WPITCH + lr];
        d[0 * WPITCH] = w.x; d[1 * WPITCH] = w.y;
        d[2 * WPITCH] = w.z; d[3 * WPITCH] = w.w;
    }

    float gpre0 = Gt[(size_t)(0 * HID + j0 + ju) * 64 + bb];
    float gpre1 = Gt[(size_t)(1 * HID + j0 + ju) * 64 + bb];
    float gpre2 = Gt[(size_t)(2 * HID + j0 + ju) * 64 + bb];
    float gpre3 = Gt[(size_t)(3 * HID + j0 + ju) * 64 + bb];
    float hold = hin[(j0 + ju) * 64 + bb];
    float cold = g_Cst[(j0 + ju) * 64 + bb];
    int tok = is_enc ? input_lines[t * 64 + bb] : 1;

    float acc[4][4] = {};

    asm volatile("cp.async.wait_group 0;");
    __syncthreads();

    #pragma unroll
    for (int ch = 0; ch < 4; ch++) {
        int buf = ch & 1;
        if (ch < 3) {
            #pragma unroll
            for (int i = 0; i < 8; i++) {
                int sl = tid + i * 256;
                int k = sl >> 4, q = sl & 15;
                cp_async16(hs_base + (unsigned)(((1 - buf) * 128 + k) * HPITCH + q * 4) * 4u,
                           hin + ((ch + 1) * 128 + k) * 64 + q * 4);
            }
            asm volatile("cp.async.commit_group;");
        }
        #pragma unroll
        for (int kk = 0; kk < 32; kk++) {
            int kl = kk * 4 + s;
            float4 w  = *(const float4*)&Wsm[(size_t)(ch * 128 + kl) * WPITCH + rq * 4];
            float4 h4 = *(const float4*)&hs[(size_t)(buf * 128 + kl) * HPITCH + bq * 4];
            float wr[4] = {w.x, w.y, w.z, w.w};
            float hr[4] = {h4.x, h4.y, h4.z, h4.w};
            #pragma unroll
            for (int ri = 0; ri < 4; ri++)
                #pragma unroll
                for (int bi = 0; bi < 4; bi++)
                    acc[ri][bi] = fmaf(wr[ri], hr[bi], acc[ri][bi]);
        }
        if (ch < 3) asm volatile("cp.async.wait_group 0;");
        __syncthreads();
    }

    #pragma unroll
    for (int ri = 0; ri < 4; ri++) {
        #pragma unroll
        for (int bi = 0; bi < 4; bi++) {
            float v = acc[ri][bi];
            v += __shfl_xor_sync(0xffffffffu, v, 1);
            v += __shfl_xor_sync(0xffffffffu, v, 2);
            acc[ri][bi] = v;
        }
        if (s == ri)
            *(float4*)&gsm[(rq * 4 + ri) * HPITCH + bq * 4] =
                make_float4(acc[ri][0], acc[ri][1], acc[ri][2], acc[ri][3]);
    }
    __syncthreads();

    {
        float iv = gsm[(0  + ju) * HPITCH + bb] + gpre0;
        float fv = gsm[(4  + ju) * HPITCH + bb] + gpre1;
        float gv = gsm[(8  + ju) * HPITCH + bb] + gpre2;
        float ov = gsm[(12 + ju) * HPITCH + bb] + gpre3;
        float c2 = sigmoidf_(fv) * cold + sigmoidf_(iv) * tanhf(gv);
        float h2 = sigmoidf_(ov) * tanhf(c2);
        if (is_enc && tok == 0) { c2 = cold; h2 = hold; }
        g_Cst[(j0 + ju) * 64 + bb] = c2;
        hout[(j0 + ju) * 64 + bb] = h2;
        if (!is_enc)
            g_Hall[(size_t)(j0 + ju) * NROWS_PAD + t * 64 + bb] = h2;
    }
}

// ---------------- fp32 -> bf16 conversions ----------------------------------
__global__ __launch_bounds__(256) void conv_w_kernel(const float* __restrict__ W)
{
    long long i = (long long)blockIdx.x * 256 + threadIdx.x;   // one float4 each
    if (i * 4 >= (long long)VOCAB * HID) return;
    float4 v = *(const float4*)&W[i * 4];
    __nv_bfloat162* dst = (__nv_bfloat162*)g_Wb;
    dst[i * 2 + 0] = __floats2bfloat162_rn(v.x, v.y);
    dst[i * 2 + 1] = __floats2bfloat162_rn(v.z, v.w);
}

// transpose g_Hall [k][m] -> g_Ab [m][k] bf16 (32x32 smem tiles)
__global__ void conv_hall_kernel()
{
    __shared__ float ts[32][33];
    int k0 = blockIdx.x * 32;
    int m0 = blockIdx.y * 32;
    int tx = threadIdx.x, ty = threadIdx.y;    // (32, 8)
    #pragma unroll
    for (int i = 0; i < 4; i++)
        ts[ty + i * 8][tx] = g_Hall[(size_t)(k0 + ty + i * 8) * NROWS_PAD + m0 + tx];
    __syncthreads();
    #pragma unroll
    for (int i = 0; i < 4; i++) {
        int m = m0 + ty + i * 8;
        g_Ab[(size_t)m * HID + k0 + tx] = __float2bfloat16(ts[tx][ty + i * 8]);
    }
}

// ---------------- tensor-core projection + fused loss pieces -----------------
// C = Ab[m][k] x Wb[n][k]^T via mma.sync m16n8k16 bf16. Tile 128x128, k-chunk 32,
// 8 warps (2m x 4n), warp tile 64x32. cp.async double-buffered, XOR-swizzled
// smem ([row][64B], unit ^= (row ^ row>>2) & 3 -> conflict-free ldmatrix).
__global__ __launch_bounds__(256) void proj_tc_kernel(
    const float* __restrict__ bout,
    const int*   __restrict__ targets)
{
    __shared__ __align__(16) unsigned char smA[2][8192];
    __shared__ __align__(16) unsigned char smB[2][8192];
    __shared__ float sred[128];

    int tid  = threadIdx.x;
    int lane = tid & 31;
    int w    = tid >> 5;
    int wm   = (w & 1) * 64;
    int wn   = (w >> 1) * 32;
    int n0 = blockIdx.x * 128;
    int m0 = blockIdx.y * 128;

    if (tid < 128) sred[tid] = 0.0f;

    unsigned baseA = smem_u32(smA);
    unsigned baseB = smem_u32(smB);

    // tile loader: chunk c (32 k) into buffer buf
    auto load_tiles = [&](int c, int buf) {
        #pragma unroll
        for (int i = 0; i < 2; i++) {
            int sl = tid + i * 256;            // 512 slots = 128 rows x 4 units
            int row = sl >> 2, u = sl & 3;
            int su = (u ^ (row ^ (row >> 2))) & 3;
            unsigned off = (unsigned)(buf * 8192 + row * 64 + su * 16);
            cp_async16(baseA + off, g_Ab + (size_t)(m0 + row) * HID + c * 32 + u * 8);
            cp_async16(baseB + off, g_Wb + (size_t)(n0 + row) * HID + c * 32 + u * 8);
        }
    };

    float acc[4][4][4] = {};
    load_tiles(0, 0);
    asm volatile("cp.async.commit_group;");

    for (int c = 0; c < 16; c++) {
        if (c < 15) {
            load_tiles(c + 1, (c + 1) & 1);
            asm volatile("cp.async.commit_group;");
            asm volatile("cp.async.wait_group 1;");
        } else {
            asm volatile("cp.async.wait_group 0;");
        }
        __syncthreads();
        int buf = c & 1;
        #pragma unroll
        for (int ks = 0; ks < 2; ks++) {
            unsigned ar[4][4];
            #pragma unroll
            for (int mi = 0; mi < 4; mi++) {
                int row = wm + mi * 16 + (lane & 15);
                int u = ks * 2 + (lane >> 4);
                int su = (u ^ (row ^ (row >> 2))) & 3;
                ldsm_x4(ar[mi][0], ar[mi][1], ar[mi][2], ar[mi][3],
                        baseA + (unsigned)(buf * 8192 + row * 64 + su * 16));
            }
            unsigned br[2][4];
            #pragma unroll
            for (int pp = 0; pp < 2; pp++) {
                int row = wn + pp * 16 + ((lane >> 4) << 3) + (lane & 7);
                int u = ks * 2 + ((lane >> 3) & 1);
                int su = (u ^ (row ^ (row >> 2))) & 3;
                ldsm_x4(br[pp][0], br[pp][1], br[pp][2], br[pp][3],
                        baseB + (unsigned)(buf * 8192 + row * 64 + su * 16));
            }
            #pragma unroll
            for (int mi = 0; mi < 4; mi++)
                #pragma unroll
                for (int ni = 0; ni < 4; ni++)
                    mma16816(acc[mi][ni], ar[mi],
                             br[ni >> 1][(ni & 1) * 2], br[ni >> 1][(ni & 1) * 2 + 1]);
        }
        __syncthreads();
    }

    // epilogue: bias, exp-sum, target capture; reduce per block row then global
    int gid = lane >> 2, tig = lane & 3;
    #pragma unroll
    for (int mi = 0; mi < 4; mi++) {
        #pragma unroll
        for (int h = 0; h < 2; h++) {
            int rl = wm + mi * 16 + gid + h * 8;
            int gm = m0 + rl;
            bool valid = (gm < NROWS);
            int tgt = valid ? targets[gm + BATCH] : -1;
            float s = 0.0f;
            #pragma unroll
            for (int ni = 0; ni < 4; ni++) {
                #pragma unroll
                for (int r = 0; r < 2; r++) {
                    int col = n0 + wn + ni * 8 + tig * 2 + r;
                    float logit = acc[mi][ni][h * 2 + r] + bout[col];
                    s += __expf(logit);
                    if (valid && col == tgt) g_rowtgt[gm] = logit;
                }
            }
            s += __shfl_xor_sync(0xffffffffu, s, 1);
            s += __shfl_xor_sync(0xffffffffu, s, 2);
            if (tig == 0) atomicAdd(&sred[rl], s);
        }
    }
    __syncthreads();
    if (tid < 128 && (m0 + tid) < NROWS)
        atomicAdd(&g_rowsum[m0 + tid], sred[tid]);
}

// ---------------- final loss reduction ---------------------------------------
__global__ void loss_reduce_kernel(float* __restrict__ out)
{
    __shared__ float sbuf[256];
    int tid = threadIdx.x;
    float s = 0.0f;
    for (int r = tid; r < NROWS; r += 256)
        s += logf(g_rowsum[r]) - g_rowtgt[r];
    sbuf[tid] = s;
    __syncthreads();
    for (int o = 128; o > 0; o >>= 1) {
        if (tid < o) sbuf[tid] += sbuf[tid + o];
        __syncthreads();
    }
    if (tid == 0) out[0] = sbuf[0] / (float)BATCH;
}

// ---------------- launch -----------------------------------------------------
extern "C" void kernel_launch(void* const* d_in, const int* in_sizes, int n_in,
                              void* d_out, int out_size)
{
    (void)in_sizes; (void)n_in; (void)out_size;
    const int*   input_lines  = (const int*)  d_in[0];
    const int*   target_lines = (const int*)  d_in[1];
    const float* emb_in       = (const float*)d_in[2];
    const float* emb_tgt      = (const float*)d_in[3];
    const float* W_ih_e       = (const float*)d_in[4];
    const float* W_hh_e       = (const float*)d_in[5];
    const float* b_ih_e       = (const float*)d_in[6];
    const float* b_hh_e       = (const float*)d_in[7];
    const float* W_ih_d       = (const float*)d_in[8];
    const float* W_hh_d       = (const float*)d_in[9];
    const float* b_ih_d       = (const float*)d_in[10];
    const float* b_hh_d       = (const float*)d_in[11];
    const float* W_out        = (const float*)d_in[12];
    const float* b_out        = (const float*)d_in[13];
    float* out = (float*)d_out;

    const int SMEM_BYTES = (512 * WPITCH + 2 * 128 * HPITCH + 16 * HPITCH) * 4;
    cudaFuncSetAttribute(lstm_step,
                         cudaFuncAttributeMaxDynamicSharedMemorySize,
                         SMEM_BYTES);

    init_kernel<<<(HID * BATCH + 255) / 256, 256>>>();

    embed_gemm128<<<dim3(G4 / 128, 24), 256>>>(
        input_lines, emb_in, W_ih_e, b_ih_e, b_hh_e, 1, SRC_LEN * BATCH);
    embed_gemm128<<<dim3(G4 / 128, 24), 256>>>(
        target_lines, emb_tgt, W_ih_d, b_ih_d, b_hh_d, 0, DSTEPS * BATCH);

    conv_w_kernel<<<(VOCAB * HID / 4 + 255) / 256, 256>>>(W_out);

    int p = 0;
    for (int t = 0; t < SRC_LEN; t++) {
        lstm_step<<<HID / 4, 256, SMEM_BYTES>>>(W_hh_e, input_lines, 1, t, p);
        p ^= 1;
    }
    for (int t = 0; t < DSTEPS; t++) {
        lstm_step<<<HID / 4, 256, SMEM_BYTES>>>(W_hh_d, input_lines, 0, t, p);
        p ^= 1;
    }

    conv_hall_kernel<<<dim3(HID / 32, NROWS_PAD / 32), dim3(32, 8)>>>();

    proj_tc_kernel<<<dim3(VOCAB / 128, NROWS_PAD / 128), 256>>>(
        b_out, target_lines);

    loss_reduce_kernel<<<1, 256>>>(out);
}

// round 11
// speedup vs baseline: 2.0154x; 1.0246x over previous
#include <cuda_runtime.h>
#include <cuda_bf16.h>
#include <math.h>

#define SRC_LEN 48
#define TGT_LEN 48
#define BATCH   64
#define HID     512
#define G4      2048
#define VOCAB   32000
#define DSTEPS  47
#define NROWS   3008
#define NROWS_PAD 3072
#define NB      128          // persistent blocks: 1/SM, <=148 SMs -> co-resident
#define WP      20           // Wst pitch (floats): banks 20s%32 distinct per phase
#define HP      68           // hs/gsm pitch

// ---------------- scratch (device globals; device-code access ONLY) ---------
__device__ float g_Ge[SRC_LEN * 4 * HID * BATCH];   // [t][g][j][b]
__device__ float g_Gd[DSTEPS  * 4 * HID * BATCH];   // [t][g][j][b]
__device__ float g_Hpp[2][HID * BATCH];             // h' [j][b], ping-pong
__device__ __nv_bfloat16 g_Ab[NROWS_PAD * HID];     // decoder h bf16 [m][k]; pad rows stay 0
__device__ __nv_bfloat16 g_Wb[VOCAB * HID];         // W_out bf16 [n][k]
__device__ float g_rowsum[NROWS];
__device__ float g_rowtgt[NROWS];
__device__ volatile unsigned g_gen;
__device__ unsigned g_cnt;

__device__ __forceinline__ float sigmoidf_(float x) {
    return 1.0f / (1.0f + __expf(-x));
}
__device__ __forceinline__ unsigned smem_u32(const void* p) {
    return (unsigned)__cvta_generic_to_shared(p);
}
__device__ __forceinline__ void cp_async16(unsigned s, const void* g) {
    asm volatile("cp.async.cg.shared.global [%0], [%1], 16;" :: "r"(s), "l"(g));
}
__device__ __forceinline__ void ldsm_x4(unsigned& r0, unsigned& r1,
                                        unsigned& r2, unsigned& r3, unsigned a) {
    asm volatile("ldmatrix.sync.aligned.m8n8.x4.shared.b16 {%0,%1,%2,%3}, [%4];"
                 : "=r"(r0), "=r"(r1), "=r"(r2), "=r"(r3) : "r"(a));
}
__device__ __forceinline__ void mma16816(float* d, const unsigned* a,
                                         unsigned b0, unsigned b1) {
    asm volatile(
        "mma.sync.aligned.m16n8k16.row.col.f32.bf16.bf16.f32 "
        "{%0,%1,%2,%3}, {%4,%5,%6,%7}, {%8,%9}, {%0,%1,%2,%3};"
        : "+f"(d[0]), "+f"(d[1]), "+f"(d[2]), "+f"(d[3])
        : "r"(a[0]), "r"(a[1]), "r"(a[2]), "r"(a[3]), "r"(b0), "r"(b1));
}

// ---------------- grid-wide barrier (all NB blocks co-resident) -------------
__device__ __forceinline__ void grid_sync() {
    __syncthreads();
    if (threadIdx.x == 0) {
        __threadfence();                       // release
        unsigned my = g_gen;
        if (atomicAdd(&g_cnt, 1u) == NB - 1u) {
            g_cnt = 0u;
            __threadfence();
            g_gen = my + 1u;
        } else {
            while (g_gen == my) { }
        }
        __threadfence();                       // acquire
    }
    __syncthreads();
}

// ---------------- init: zero rowsum -----------------------------------------
__global__ void init_kernel() {
    int i = blockIdx.x * blockDim.x + threadIdx.x;
    if (i < NROWS) g_rowsum[i] = 0.0f;
}

// ---------------- embed + input-gate GEMM (unchanged, measured-good) --------
__global__ __launch_bounds__(256) void embed_gemm128(
    const int*   __restrict__ toks,
    const float* __restrict__ emb,
    const float* __restrict__ W,
    const float* __restrict__ b1,
    const float* __restrict__ b2,
    int is_enc,
    int R)
{
    __shared__ float As[16][132];
    __shared__ float Bs[16][132];
    float* __restrict__ Gout = is_enc ? g_Ge : g_Gd;

    int m0 = blockIdx.y * 128;
    int n0 = blockIdx.x * 128;
    int tid = threadIdx.x;
    int tx = tid & 15;
    int ty = tid >> 4;
    float acc[8][8] = {};

    for (int k0 = 0; k0 < HID; k0 += 16) {
        #pragma unroll
        for (int l = 0; l < 2; l++) {
            int idx = tid + l * 256;
            int m   = idx >> 2;
            int kq  = idx & 3;
            int gm  = m0 + m;
            int tok = (gm < R) ? toks[gm] : 0;
            float4 a = make_float4(0.f, 0.f, 0.f, 0.f);
            if (tok != 0) a = *(const float4*)&emb[(size_t)tok * HID + k0 + kq * 4];
            As[kq*4+0][m] = a.x; As[kq*4+1][m] = a.y;
            As[kq*4+2][m] = a.z; As[kq*4+3][m] = a.w;
            float4 w = *(const float4*)&W[(size_t)(n0 + m) * HID + k0 + kq * 4];
            Bs[kq*4+0][m] = w.x; Bs[kq*4+1][m] = w.y;
            Bs[kq*4+2][m] = w.z; Bs[kq*4+3][m] = w.w;
        }
        __syncthreads();
        #pragma unroll
        for (int k = 0; k < 16; k++) {
            float4 a0 = *(const float4*)&As[k][ty * 4];
            float4 a1 = *(const float4*)&As[k][64 + ty * 4];
            float4 w0 = *(const float4*)&Bs[k][tx * 4];
            float4 w1 = *(const float4*)&Bs[k][64 + tx * 4];
            float ar[8] = {a0.x, a0.y, a0.z, a0.w, a1.x, a1.y, a1.z, a1.w};
            float wr[8] = {w0.x, w0.y, w0.z, w0.w, w1.x, w1.y, w1.z, w1.w};
            #pragma unroll
            for (int i = 0; i < 8; i++)
                #pragma unroll
                for (int j = 0; j < 8; j++)
                    acc[i][j] = fmaf(ar[i], wr[j], acc[i][j]);
        }
        __syncthreads();
    }

    #pragma unroll
    for (int i = 0; i < 8; i++) {
        int gm = m0 + (i < 4 ? ty * 4 + i : 64 + ty * 4 + (i - 4));
        if (gm >= R) continue;
        int t = gm >> 6;
        int b = gm & 63;
        #pragma unroll
        for (int j = 0; j < 8; j++) {
            int gn = n0 + (j < 4 ? tx * 4 + j : 64 + tx * 4 + (j - 4));
            float v = acc[i][j] + b1[gn] + b2[gn];
            int g  = gn >> 9;
            int jj = gn & 511;
            Gout[(size_t)((t * 4 + g) * 512 + jj) * 64 + b] = v;
        }
    }
}

// ---------------- persistent LSTM recurrence (95 steps, 1 launch) -----------
// Block owns j0=bid*4..+3 -> 16 gate rows (lr = g*4 + jj). Both W_hh slices
// cached k-major in smem ONCE; c in registers; h ping-pongs via global [j][b],
// staged per-step in 128-k cp.async double-buffered chunks.
// GEMM map: s=tid&15 (16-way k-split), rq=(tid>>4)&1 (8-row half), bq=tid>>5
// (8 batch). acc[8][8]: 64 B LDS per 64 FMA = 1 B/FMA (port-balanced).
// Update map: bb=tid&63, ju=tid>>6. Decoder writes bf16 g_Ab directly.
__global__ void __launch_bounds__(256, 1) lstm_persist(
    const float* __restrict__ Whe,
    const float* __restrict__ Whd,
    const int*   __restrict__ input_lines)
{
    extern __shared__ float sm[];
    float* Wst = sm;                         // [2][512][WP]
    float* hs  = sm + 2 * 512 * WP;          // [2][128][HP]
    float* gsm = hs + 2 * 128 * HP;          // [16][HP]

    int tid = threadIdx.x;
    int bid = blockIdx.x;
    int j0  = bid * 4;
    int s   = tid & 15;
    int rq  = (tid >> 4) & 1;
    int bq  = tid >> 5;
    int bb  = tid & 63;
    int ju  = tid >> 6;

    unsigned hs_base = smem_u32(hs);

    // one-time: stage both W_hh slices k-major; col lr = g*4 + jj
    for (int mat = 0; mat < 2; mat++) {
        const float* W = mat ? Whd : Whe;
        for (int sl = tid; sl < 16 * 128; sl += 256) {
            int lr = sl >> 7;                // 0..15
            int kq = sl & 127;               // float4 idx along k
            int g = lr >> 2, jj = lr & 3;
            float4 w = *(const float4*)&W[(size_t)(g * HID + j0 + jj) * HID + kq * 4];
            float* d = &Wst[(size_t)(mat * 512 + kq * 4) * WP + lr];
            d[0 * WP] = w.x; d[1 * WP] = w.y;
            d[2 * WP] = w.z; d[3 * WP] = w.w;
        }
    }
    g_Hpp[0][(j0 + ju) * 64 + bb] = 0.0f;
    float c_reg = 0.0f;
    grid_sync();

    int p = 0;
    for (int step = 0; step < SRC_LEN + DSTEPS; step++) {
        int is_enc = (step < SRC_LEN) ? 1 : 0;
        int t = is_enc ? step : step - SRC_LEN;
        const float* __restrict__ hin  = g_Hpp[p];
        float*       __restrict__ hout = g_Hpp[1 - p];
        const float* __restrict__ Gt =
            (is_enc ? g_Ge : g_Gd) + (size_t)t * 4 * HID * BATCH;
        const float* __restrict__ Wm = Wst + (size_t)(is_enc ? 0 : 1) * 512 * WP;

        // kick off h chunk 0 (k 0..127)
        #pragma unroll
        for (int i = 0; i < 8; i++) {
            int sl = tid + i * 256;           // 2048 16B slots
            int k = sl >> 4, q = sl & 15;
            cp_async16(hs_base + (unsigned)(k * HP + q * 4) * 4u,
                       hin + k * 64 + q * 4);
        }
        asm volatile("cp.async.commit_group;");

        // update-path early loads
        float gpre0 = Gt[(size_t)(0 * HID + j0 + ju) * 64 + bb];
        float gpre1 = Gt[(size_t)(1 * HID + j0 + ju) * 64 + bb];
        float gpre2 = Gt[(size_t)(2 * HID + j0 + ju) * 64 + bb];
        float gpre3 = Gt[(size_t)(3 * HID + j0 + ju) * 64 + bb];
        float hold = hin[(j0 + ju) * 64 + bb];
        int tok = is_enc ? input_lines[t * 64 + bb] : 1;

        float acc[8][8] = {};

        asm volatile("cp.async.wait_group 0;");
        __syncthreads();

        #pragma unroll
        for (int ch = 0; ch < 4; ch++) {
            int buf = ch & 1;
            if (ch < 3) {
                #pragma unroll
                for (int i = 0; i < 8; i++) {
                    int sl = tid + i * 256;
                    int k = sl >> 4, q = sl & 15;
                    cp_async16(hs_base + (unsigned)(((1 - buf) * 128 + k) * HP + q * 4) * 4u,
                               hin + ((ch + 1) * 128 + k) * 64 + q * 4);
                }
                asm volatile("cp.async.commit_group;");
            }
            #pragma unroll
            for (int kk = 0; kk < 8; kk++) {
                int kl = kk * 16 + s;                 // 0..127 within chunk
                const float* wp = &Wm[(size_t)(ch * 128 + kl) * WP + rq * 8];
                float4 wa = *(const float4*)wp;
                float4 wb = *(const float4*)(wp + 4);
                const float* hp = &hs[(size_t)(buf * 128 + kl) * HP + bq * 8];
                float4 ha = *(const float4*)hp;
                float4 hb = *(const float4*)(hp + 4);
                float wr[8] = {wa.x, wa.y, wa.z, wa.w, wb.x, wb.y, wb.z, wb.w};
                float hr[8] = {ha.x, ha.y, ha.z, ha.w, hb.x, hb.y, hb.z, hb.w};
                #pragma unroll
                for (int ri = 0; ri < 8; ri++)
                    #pragma unroll
                    for (int bi = 0; bi < 8; bi++)
                        acc[ri][bi] = fmaf(wr[ri], hr[bi], acc[ri][bi]);
            }
            if (ch < 3) asm volatile("cp.async.wait_group 0;");
            __syncthreads();
        }

        // per-row: reduce over 16 k-split lanes (lane bits 0..3), then emit
        #pragma unroll
        for (int ri = 0; ri < 8; ri++) {
            #pragma unroll
            for (int bi = 0; bi < 8; bi++) {
                float v = acc[ri][bi];
                v += __shfl_xor_sync(0xffffffffu, v, 1);
                v += __shfl_xor_sync(0xffffffffu, v, 2);
                v += __shfl_xor_sync(0xffffffffu, v, 4);
                v += __shfl_xor_sync(0xffffffffu, v, 8);
                acc[ri][bi] = v;
            }
            if (s == ri)
                *(float4*)&gsm[(rq * 8 + ri) * HP + bq * 8] =
                    make_float4(acc[ri][0], acc[ri][1], acc[ri][2], acc[ri][3]);
            if (s == ri + 8)
                *(float4*)&gsm[(rq * 8 + ri) * HP + bq * 8 + 4] =
                    make_float4(acc[ri][4], acc[ri][5], acc[ri][6], acc[ri][7]);
        }
        __syncthreads();

        // fused cell update; gate rows lr = g*4 + ju
        {
            float iv = gsm[(0  + ju) * HP + bb] + gpre0;
            float fv = gsm[(4  + ju) * HP + bb] + gpre1;
            float gv = gsm[(8  + ju) * HP + bb] + gpre2;
            float ov = gsm[(12 + ju) * HP + bb] + gpre3;
            float c2 = sigmoidf_(fv) * c_reg + sigmoidf_(iv) * tanhf(gv);
            float h2 = sigmoidf_(ov) * tanhf(c2);
            if (is_enc && tok == 0) { c2 = c_reg; h2 = hold; }
            c_reg = c2;
            hout[(j0 + ju) * 64 + bb] = h2;
            if (!is_enc)
                g_Ab[(size_t)(t * 64 + bb) * HID + j0 + ju] = __float2bfloat16(h2);
        }
        grid_sync();
        p ^= 1;
    }
}

// ---------------- fp32 -> bf16 W conversion ----------------------------------
__global__ __launch_bounds__(256) void conv_w_kernel(const float* __restrict__ W)
{
    long long i = (long long)blockIdx.x * 256 + threadIdx.x;   // one float4 each
    if (i * 4 >= (long long)VOCAB * HID) return;
    float4 v = *(const float4*)&W[i * 4];
    __nv_bfloat162* dst = (__nv_bfloat162*)g_Wb;
    dst[i * 2 + 0] = __floats2bfloat162_rn(v.x, v.y);
    dst[i * 2 + 1] = __floats2bfloat162_rn(v.z, v.w);
}

// ---------------- tensor-core projection + fused loss pieces -----------------
__global__ __launch_bounds__(256) void proj_tc_kernel(
    const float* __restrict__ bout,
    const int*   __restrict__ targets)
{
    __shared__ __align__(16) unsigned char smA[2][8192];
    __shared__ __align__(16) unsigned char smB[2][8192];
    __shared__ float sred[128];

    int tid  = threadIdx.x;
    int lane = tid & 31;
    int w    = tid >> 5;
    int wm   = (w & 1) * 64;
    int wn   = (w >> 1) * 32;
    int n0 = blockIdx.x * 128;
    int m0 = blockIdx.y * 128;

    if (tid < 128) sred[tid] = 0.0f;

    unsigned baseA = smem_u32(smA);
    unsigned baseB = smem_u32(smB);

    auto load_tiles = [&](int c, int buf) {
        #pragma unroll
        for (int i = 0; i < 2; i++) {
            int sl = tid + i * 256;
            int row = sl >> 2, u = sl & 3;
            int su = (u ^ (row ^ (row >> 2))) & 3;
            unsigned off = (unsigned)(buf * 8192 + row * 64 + su * 16);
            cp_async16(baseA + off, g_Ab + (size_t)(m0 + row) * HID + c * 32 + u * 8);
            cp_async16(baseB + off, g_Wb + (size_t)(n0 + row) * HID + c * 32 + u * 8);
        }
    };

    float acc[4][4][4] = {};
    load_tiles(0, 0);
    asm volatile("cp.async.commit_group;");

    for (int c = 0; c < 16; c++) {
        if (c < 15) {
            load_tiles(c + 1, (c + 1) & 1);
            asm volatile("cp.async.commit_group;");
            asm volatile("cp.async.wait_group 1;");
        } else {
            asm volatile("cp.async.wait_group 0;");
        }
        __syncthreads();
        int buf = c & 1;
        #pragma unroll
        for (int ks = 0; ks < 2; ks++) {
            unsigned ar[4][4];
            #pragma unroll
            for (int mi = 0; mi < 4; mi++) {
                int row = wm + mi * 16 + (lane & 15);
                int u = ks * 2 + (lane >> 4);
                int su = (u ^ (row ^ (row >> 2))) & 3;
                ldsm_x4(ar[mi][0], ar[mi][1], ar[mi][2], ar[mi][3],
                        baseA + (unsigned)(buf * 8192 + row * 64 + su * 16));
            }
            unsigned br[2][4];
            #pragma unroll
            for (int pp = 0; pp < 2; pp++) {
                int row = wn + pp * 16 + ((lane >> 4) << 3) + (lane & 7);
                int u = ks * 2 + ((lane >> 3) & 1);
                int su = (u ^ (row ^ (row >> 2))) & 3;
                ldsm_x4(br[pp][0], br[pp][1], br[pp][2], br[pp][3],
                        baseB + (unsigned)(buf * 8192 + row * 64 + su * 16));
            }
            #pragma unroll
            for (int mi = 0; mi < 4; mi++)
                #pragma unroll
                for (int ni = 0; ni < 4; ni++)
                    mma16816(acc[mi][ni], ar[mi],
                             br[ni >> 1][(ni & 1) * 2], br[ni >> 1][(ni & 1) * 2 + 1]);
        }
        __syncthreads();
    }

    int gid = lane >> 2, tig = lane & 3;
    #pragma unroll
    for (int mi = 0; mi < 4; mi++) {
        #pragma unroll
        for (int h = 0; h < 2; h++) {
            int rl = wm + mi * 16 + gid + h * 8;
            int gm = m0 + rl;
            bool valid = (gm < NROWS);
            int tgt = valid ? targets[gm + BATCH] : -1;
            float s = 0.0f;
            #pragma unroll
            for (int ni = 0; ni < 4; ni++) {
                #pragma unroll
                for (int r = 0; r < 2; r++) {
                    int col = n0 + wn + ni * 8 + tig * 2 + r;
                    float logit = acc[mi][ni][h * 2 + r] + bout[col];
                    s += __expf(logit);
                    if (valid && col == tgt) g_rowtgt[gm] = logit;
                }
            }
            s += __shfl_xor_sync(0xffffffffu, s, 1);
            s += __shfl_xor_sync(0xffffffffu, s, 2);
            if (tig == 0) atomicAdd(&sred[rl], s);
        }
    }
    __syncthreads();
    if (tid < 128 && (m0 + tid) < NROWS)
        atomicAdd(&g_rowsum[m0 + tid], sred[tid]);
}

// ---------------- final loss reduction ---------------------------------------
__global__ void loss_reduce_kernel(float* __restrict__ out)
{
    __shared__ float sbuf[256];
    int tid = threadIdx.x;
    float s = 0.0f;
    for (int r = tid; r < NROWS; r += 256)
        s += logf(g_rowsum[r]) - g_rowtgt[r];
    sbuf[tid] = s;
    __syncthreads();
    for (int o = 128; o > 0; o >>= 1) {
        if (tid < o) sbuf[tid] += sbuf[tid + o];
        __syncthreads();
    }
    if (tid == 0) out[0] = sbuf[0] / (float)BATCH;
}

// ---------------- launch -----------------------------------------------------
extern "C" void kernel_launch(void* const* d_in, const int* in_sizes, int n_in,
                              void* d_out, int out_size)
{
    (void)in_sizes; (void)n_in; (void)out_size;
    const int*   input_lines  = (const int*)  d_in[0];
    const int*   target_lines = (const int*)  d_in[1];
    const float* emb_in       = (const float*)d_in[2];
    const float* emb_tgt      = (const float*)d_in[3];
    const float* W_ih_e       = (const float*)d_in[4];
    const float* W_hh_e       = (const float*)d_in[5];
    const float* b_ih_e       = (const float*)d_in[6];
    const float* b_hh_e       = (const float*)d_in[7];
    const float* W_ih_d       = (const float*)d_in[8];
    const float* W_hh_d       = (const float*)d_in[9];
    const float* b_ih_d       = (const float*)d_in[10];
    const float* b_hh_d       = (const float*)d_in[11];
    const float* W_out        = (const float*)d_in[12];
    const float* b_out        = (const float*)d_in[13];
    float* out = (float*)d_out;

    const int SMEM_BYTES = (2 * 512 * WP + 2 * 128 * HP + 16 * HP) * 4;
    cudaFuncSetAttribute(lstm_persist,
                         cudaFuncAttributeMaxDynamicSharedMemorySize,
                         SMEM_BYTES);

    init_kernel<<<(NROWS + 255) / 256, 256>>>();

    embed_gemm128<<<dim3(G4 / 128, 24), 256>>>(
        input_lines, emb_in, W_ih_e, b_ih_e, b_hh_e, 1, SRC_LEN * BATCH);
    embed_gemm128<<<dim3(G4 / 128, 24), 256>>>(
        target_lines, emb_tgt, W_ih_d, b_ih_d, b_hh_d, 0, DSTEPS * BATCH);

    conv_w_kernel<<<(VOCAB * HID / 4 + 255) / 256, 256>>>(W_out);

    lstm_persist<<<NB, 256, SMEM_BYTES>>>(W_hh_e, W_hh_d, input_lines);

    proj_tc_kernel<<<dim3(VOCAB / 128, NROWS_PAD / 128), 256>>>(
        b_out, target_lines);

    loss_reduce_kernel<<<1, 256>>>(out);
}

// round 12
// speedup vs baseline: 2.0827x; 1.0334x over previous
#include <cuda_runtime.h>
#include <cuda_bf16.h>
#include <math.h>

#define SRC_LEN 48
#define TGT_LEN 48
#define BATCH   64
#define HID     512
#define G4      2048
#define VOCAB   32000
#define DSTEPS  47
#define NROWS   3008
#define NROWS_PAD 3072
#define NB      128          // persistent blocks: 1/SM, co-resident
#define WP      20           // Wst pitch (floats): banks 20s%32 distinct per phase
#define HP      68           // hs/gsm pitch

// ---------------- scratch (device globals; device-code access ONLY) ---------
__device__ float g_Ge[SRC_LEN * 4 * HID * BATCH];   // [t][g][j][b]
__device__ float g_Gd[DSTEPS  * 4 * HID * BATCH];   // [t][g][j][b]
__device__ float g_Hpp[2][HID * BATCH];             // h' [j][b], ping-pong
__device__ __nv_bfloat16 g_Ab[NROWS_PAD * HID];     // decoder h bf16 [m][k]; pad rows stay 0
__device__ __nv_bfloat16 g_Wb[VOCAB * HID];         // W_out bf16 [n][k]
__device__ float g_rowsum[NROWS];
__device__ float g_rowtgt[NROWS];
__device__ unsigned g_gen;
__device__ unsigned g_cnt;

__device__ __forceinline__ float sigmoidf_(float x) {
    return 1.0f / (1.0f + __expf(-x));
}
__device__ __forceinline__ float tanh_fast(float x) {
    float y;
    asm("tanh.approx.f32 %0, %1;" : "=f"(y) : "f"(x));
    return y;
}
__device__ __forceinline__ unsigned smem_u32(const void* p) {
    return (unsigned)__cvta_generic_to_shared(p);
}
__device__ __forceinline__ void cp_async16(unsigned s, const void* g) {
    asm volatile("cp.async.cg.shared.global [%0], [%1], 16;" :: "r"(s), "l"(g));
}
__device__ __forceinline__ void ldsm_x4(unsigned& r0, unsigned& r1,
                                        unsigned& r2, unsigned& r3, unsigned a) {
    asm volatile("ldmatrix.sync.aligned.m8n8.x4.shared.b16 {%0,%1,%2,%3}, [%4];"
                 : "=r"(r0), "=r"(r1), "=r"(r2), "=r"(r3) : "r"(a));
}
__device__ __forceinline__ void mma16816(float* d, const unsigned* a,
                                         unsigned b0, unsigned b1) {
    asm volatile(
        "mma.sync.aligned.m16n8k16.row.col.f32.bf16.bf16.f32 "
        "{%0,%1,%2,%3}, {%4,%5,%6,%7}, {%8,%9}, {%0,%1,%2,%3};"
        : "+f"(d[0]), "+f"(d[1]), "+f"(d[2]), "+f"(d[3])
        : "r"(a[0]), "r"(a[1]), "r"(a[2]), "r"(a[3]), "r"(b0), "r"(b1));
}

// ---------------- grid-wide barrier (CG pattern: release-arrive / acquire) --
__device__ __forceinline__ void grid_sync() {
    __syncthreads();
    if (threadIdx.x == 0) {
        unsigned my;
        asm volatile("ld.relaxed.gpu.u32 %0, [%1];" : "=r"(my) : "l"(&g_gen));
        unsigned prev;
        asm volatile("atom.add.release.gpu.u32 %0, [%1], 1;"
                     : "=r"(prev) : "l"(&g_cnt));
        if (prev == NB - 1u) {
            asm volatile("st.relaxed.gpu.u32 [%0], 0;" :: "l"(&g_cnt));
            asm volatile("st.release.gpu.u32 [%0], %1;" :: "l"(&g_gen), "r"(my + 1u));
        } else {
            unsigned cur;
            do {
                asm volatile("ld.acquire.gpu.u32 %0, [%1];" : "=r"(cur) : "l"(&g_gen));
            } while (cur == my);
        }
    }
    __syncthreads();
}

// ---------------- init: zero rowsum -----------------------------------------
__global__ void init_kernel() {
    int i = blockIdx.x * blockDim.x + threadIdx.x;
    if (i < NROWS) g_rowsum[i] = 0.0f;
}

// ---------------- embed + input-gate GEMM (unchanged, measured-good) --------
__global__ __launch_bounds__(256) void embed_gemm128(
    const int*   __restrict__ toks,
    const float* __restrict__ emb,
    const float* __restrict__ W,
    const float* __restrict__ b1,
    const float* __restrict__ b2,
    int is_enc,
    int R)
{
    __shared__ float As[16][132];
    __shared__ float Bs[16][132];
    float* __restrict__ Gout = is_enc ? g_Ge : g_Gd;

    int m0 = blockIdx.y * 128;
    int n0 = blockIdx.x * 128;
    int tid = threadIdx.x;
    int tx = tid & 15;
    int ty = tid >> 4;
    float acc[8][8] = {};

    for (int k0 = 0; k0 < HID; k0 += 16) {
        #pragma unroll
        for (int l = 0; l < 2; l++) {
            int idx = tid + l * 256;
            int m   = idx >> 2;
            int kq  = idx & 3;
            int gm  = m0 + m;
            int tok = (gm < R) ? toks[gm] : 0;
            float4 a = make_float4(0.f, 0.f, 0.f, 0.f);
            if (tok != 0) a = *(const float4*)&emb[(size_t)tok * HID + k0 + kq * 4];
            As[kq*4+0][m] = a.x; As[kq*4+1][m] = a.y;
            As[kq*4+2][m] = a.z; As[kq*4+3][m] = a.w;
            float4 w = *(const float4*)&W[(size_t)(n0 + m) * HID + k0 + kq * 4];
            Bs[kq*4+0][m] = w.x; Bs[kq*4+1][m] = w.y;
            Bs[kq*4+2][m] = w.z; Bs[kq*4+3][m] = w.w;
        }
        __syncthreads();
        #pragma unroll
        for (int k = 0; k < 16; k++) {
            float4 a0 = *(const float4*)&As[k][ty * 4];
            float4 a1 = *(const float4*)&As[k][64 + ty * 4];
            float4 w0 = *(const float4*)&Bs[k][tx * 4];
            float4 w1 = *(const float4*)&Bs[k][64 + tx * 4];
            float ar[8] = {a0.x, a0.y, a0.z, a0.w, a1.x, a1.y, a1.z, a1.w};
            float wr[8] = {w0.x, w0.y, w0.z, w0.w, w1.x, w1.y, w1.z, w1.w};
            #pragma unroll
            for (int i = 0; i < 8; i++)
                #pragma unroll
                for (int j = 0; j < 8; j++)
                    acc[i][j] = fmaf(ar[i], wr[j], acc[i][j]);
        }
        __syncthreads();
    }

    #pragma unroll
    for (int i = 0; i < 8; i++) {
        int gm = m0 + (i < 4 ? ty * 4 + i : 64 + ty * 4 + (i - 4));
        if (gm >= R) continue;
        int t = gm >> 6;
        int b = gm & 63;
        #pragma unroll
        for (int j = 0; j < 8; j++) {
            int gn = n0 + (j < 4 ? tx * 4 + j : 64 + tx * 4 + (j - 4));
            float v = acc[i][j] + b1[gn] + b2[gn];
            int g  = gn >> 9;
            int jj = gn & 511;
            Gout[(size_t)((t * 4 + g) * 512 + jj) * 64 + b] = v;
        }
    }
}

// ---------------- persistent LSTM recurrence (95 steps, 1 launch) -----------
// As round 10, plus: 3-deep cp.async ring (prefetch depth 2, wait_group 1),
// relaxed-consistency grid barrier (no L1 flush; h reads are L1-bypassing),
// tanh.approx. Map: s=tid&15 (16-way k-split), rq=(tid>>4)&1, bq=tid>>5;
// acc[8][8] (1 B/FMA). Update: bb=tid&63, ju=tid>>6; c in registers.
__global__ void __launch_bounds__(256, 1) lstm_persist(
    const float* __restrict__ Whe,
    const float* __restrict__ Whd,
    const int*   __restrict__ input_lines)
{
    extern __shared__ float sm[];
    float* Wst = sm;                         // [2][512][WP]
    float* hs  = sm + 2 * 512 * WP;          // [3][128][HP] ring
    float* gsm = hs + 3 * 128 * HP;          // [16][HP]

    int tid = threadIdx.x;
    int bid = blockIdx.x;
    int j0  = bid * 4;
    int s   = tid & 15;
    int rq  = (tid >> 4) & 1;
    int bq  = tid >> 5;
    int bb  = tid & 63;
    int ju  = tid >> 6;

    unsigned hs_base = smem_u32(hs);

    // one-time: stage both W_hh slices k-major; col lr = g*4 + jj
    for (int mat = 0; mat < 2; mat++) {
        const float* W = mat ? Whd : Whe;
        for (int sl = tid; sl < 16 * 128; sl += 256) {
            int lr = sl >> 7;
            int kq = sl & 127;
            int g = lr >> 2, jj = lr & 3;
            float4 w = *(const float4*)&W[(size_t)(g * HID + j0 + jj) * HID + kq * 4];
            float* d = &Wst[(size_t)(mat * 512 + kq * 4) * WP + lr];
            d[0 * WP] = w.x; d[1 * WP] = w.y;
            d[2 * WP] = w.z; d[3 * WP] = w.w;
        }
    }
    g_Hpp[0][(j0 + ju) * 64 + bb] = 0.0f;
    float c_reg = 0.0f;
    grid_sync();

    int p = 0;
    for (int step = 0; step < SRC_LEN + DSTEPS; step++) {
        int is_enc = (step < SRC_LEN) ? 1 : 0;
        int t = is_enc ? step : step - SRC_LEN;
        const float* __restrict__ hin  = g_Hpp[p];
        float*       __restrict__ hout = g_Hpp[1 - p];
        const float* __restrict__ Gt =
            (is_enc ? g_Ge : g_Gd) + (size_t)t * 4 * HID * BATCH;
        const float* __restrict__ Wm = Wst + (size_t)(is_enc ? 0 : 1) * 512 * WP;

        // stage chunks 0 and 1 (prefetch depth 2)
        #pragma unroll
        for (int cc = 0; cc < 2; cc++) {
            #pragma unroll
            for (int i = 0; i < 8; i++) {
                int sl = tid + i * 256;           // 2048 16B slots
                int k = sl >> 4, q = sl & 15;
                cp_async16(hs_base + (unsigned)((cc * 128 + k) * HP + q * 4) * 4u,
                           hin + (cc * 128 + k) * 64 + q * 4);
            }
            asm volatile("cp.async.commit_group;");
        }

        // update-path early loads (fresh addresses each t; hold needs L1 bypass)
        float gpre0 = Gt[(size_t)(0 * HID + j0 + ju) * 64 + bb];
        float gpre1 = Gt[(size_t)(1 * HID + j0 + ju) * 64 + bb];
        float gpre2 = Gt[(size_t)(2 * HID + j0 + ju) * 64 + bb];
        float gpre3 = Gt[(size_t)(3 * HID + j0 + ju) * 64 + bb];
        float hold = __ldcg(&hin[(j0 + ju) * 64 + bb]);
        int tok = is_enc ? input_lines[t * 64 + bb] : 1;

        float acc[8][8] = {};

        #pragma unroll
        for (int ch = 0; ch < 4; ch++) {
            int buf = ch % 3;
            // wait: chunk ch landed (allow 1 newer group outstanding; ch=3 -> 0)
            if (ch < 3) asm volatile("cp.async.wait_group 1;");
            else        asm volatile("cp.async.wait_group 0;");
            __syncthreads();                      // also: ring slot (ch+2)%3 free
            if (ch < 2) {
                int nc = ch + 2;                  // prefetch chunk ch+2
                int nb_ = nc % 3;
                #pragma unroll
                for (int i = 0; i < 8; i++) {
                    int sl = tid + i * 256;
                    int k = sl >> 4, q = sl & 15;
                    cp_async16(hs_base + (unsigned)((nb_ * 128 + k) * HP + q * 4) * 4u,
                               hin + (nc * 128 + k) * 64 + q * 4);
                }
                asm volatile("cp.async.commit_group;");
            }
            #pragma unroll
            for (int kk = 0; kk < 8; kk++) {
                int kl = kk * 16 + s;
                const float* wp = &Wm[(size_t)(ch * 128 + kl) * WP + rq * 8];
                float4 wa = *(const float4*)wp;
                float4 wb = *(const float4*)(wp + 4);
                const float* hp = &hs[(size_t)(buf * 128 + kl) * HP + bq * 8];
                float4 ha = *(const float4*)hp;
                float4 hb = *(const float4*)(hp + 4);
                float wr[8] = {wa.x, wa.y, wa.z, wa.w, wb.x, wb.y, wb.z, wb.w};
                float hr[8] = {ha.x, ha.y, ha.z, ha.w, hb.x, hb.y, hb.z, hb.w};
                #pragma unroll
                for (int ri = 0; ri < 8; ri++)
                    #pragma unroll
                    for (int bi = 0; bi < 8; bi++)
                        acc[ri][bi] = fmaf(wr[ri], hr[bi], acc[ri][bi]);
            }
        }
        __syncthreads();

        // per-row: reduce over 16 k-split lanes, then emit to gsm
        #pragma unroll
        for (int ri = 0; ri < 8; ri++) {
            #pragma unroll
            for (int bi = 0; bi < 8; bi++) {
                float v = acc[ri][bi];
                v += __shfl_xor_sync(0xffffffffu, v, 1);
                v += __shfl_xor_sync(0xffffffffu, v, 2);
                v += __shfl_xor_sync(0xffffffffu, v, 4);
                v += __shfl_xor_sync(0xffffffffu, v, 8);
                acc[ri][bi] = v;
            }
            if (s == ri)
                *(float4*)&gsm[(rq * 8 + ri) * HP + bq * 8] =
                    make_float4(acc[ri][0], acc[ri][1], acc[ri][2], acc[ri][3]);
            if (s == ri + 8)
                *(float4*)&gsm[(rq * 8 + ri) * HP + bq * 8 + 4] =
                    make_float4(acc[ri][4], acc[ri][5], acc[ri][6], acc[ri][7]);
        }
        __syncthreads();

        // fused cell update; gate rows lr = g*4 + ju
        {
            float iv = gsm[(0  + ju) * HP + bb] + gpre0;
            float fv = gsm[(4  + ju) * HP + bb] + gpre1;
            float gv = gsm[(8  + ju) * HP + bb] + gpre2;
            float ov = gsm[(12 + ju) * HP + bb] + gpre3;
            float c2 = sigmoidf_(fv) * c_reg + sigmoidf_(iv) * tanh_fast(gv);
            float h2 = sigmoidf_(ov) * tanh_fast(c2);
            if (is_enc && tok == 0) { c2 = c_reg; h2 = hold; }
            c_reg = c2;
            hout[(j0 + ju) * 64 + bb] = h2;
            if (!is_enc)
                g_Ab[(size_t)(t * 64 + bb) * HID + j0 + ju] = __float2bfloat16(h2);
        }
        grid_sync();
        p ^= 1;
    }
}

// ---------------- fp32 -> bf16 W conversion ----------------------------------
__global__ __launch_bounds__(256) void conv_w_kernel(const float* __restrict__ W)
{
    long long i = (long long)blockIdx.x * 256 + threadIdx.x;
    if (i * 4 >= (long long)VOCAB * HID) return;
    float4 v = *(const float4*)&W[i * 4];
    __nv_bfloat162* dst = (__nv_bfloat162*)g_Wb;
    dst[i * 2 + 0] = __floats2bfloat162_rn(v.x, v.y);
    dst[i * 2 + 1] = __floats2bfloat162_rn(v.z, v.w);
}

// ---------------- tensor-core projection + fused loss pieces -----------------
__global__ __launch_bounds__(256) void proj_tc_kernel(
    const float* __restrict__ bout,
    const int*   __restrict__ targets)
{
    __shared__ __align__(16) unsigned char smA[2][8192];
    __shared__ __align__(16) unsigned char smB[2][8192];
    __shared__ float sred[128];

    int tid  = threadIdx.x;
    int lane = tid & 31;
    int w    = tid >> 5;
    int wm   = (w & 1) * 64;
    int wn   = (w >> 1) * 32;
    int n0 = blockIdx.x * 128;
    int m0 = blockIdx.y * 128;

    if (tid < 128) sred[tid] = 0.0f;

    unsigned baseA = smem_u32(smA);
    unsigned baseB = smem_u32(smB);

    auto load_tiles = [&](int c, int buf) {
        #pragma unroll
        for (int i = 0; i < 2; i++) {
            int sl = tid + i * 256;
            int row = sl >> 2, u = sl & 3;
            int su = (u ^ (row ^ (row >> 2))) & 3;
            unsigned off = (unsigned)(buf * 8192 + row * 64 + su * 16);
            cp_async16(baseA + off, g_Ab + (size_t)(m0 + row) * HID + c * 32 + u * 8);
            cp_async16(baseB + off, g_Wb + (size_t)(n0 + row) * HID + c * 32 + u * 8);
        }
    };

    float acc[4][4][4] = {};
    load_tiles(0, 0);
    asm volatile("cp.async.commit_group;");

    for (int c = 0; c < 16; c++) {
        if (c < 15) {
            load_tiles(c + 1, (c + 1) & 1);
            asm volatile("cp.async.commit_group;");
            asm volatile("cp.async.wait_group 1;");
        } else {
            asm volatile("cp.async.wait_group 0;");
        }
        __syncthreads();
        int buf = c & 1;
        #pragma unroll
        for (int ks = 0; ks < 2; ks++) {
            unsigned ar[4][4];
            #pragma unroll
            for (int mi = 0; mi < 4; mi++) {
                int row = wm + mi * 16 + (lane & 15);
                int u = ks * 2 + (lane >> 4);
                int su = (u ^ (row ^ (row >> 2))) & 3;
                ldsm_x4(ar[mi][0], ar[mi][1], ar[mi][2], ar[mi][3],
                        baseA + (unsigned)(buf * 8192 + row * 64 + su * 16));
            }
            unsigned br[2][4];
            #pragma unroll
            for (int pp = 0; pp < 2; pp++) {
                int row = wn + pp * 16 + ((lane >> 4) << 3) + (lane & 7);
                int u = ks * 2 + ((lane >> 3) & 1);
                int su = (u ^ (row ^ (row >> 2))) & 3;
                ldsm_x4(br[pp][0], br[pp][1], br[pp][2], br[pp][3],
                        baseB + (unsigned)(buf * 8192 + row * 64 + su * 16));
            }
            #pragma unroll
            for (int mi = 0; mi < 4; mi++)
                #pragma unroll
                for (int ni = 0; ni < 4; ni++)
                    mma16816(acc[mi][ni], ar[mi],
                             br[ni >> 1][(ni & 1) * 2], br[ni >> 1][(ni & 1) * 2 + 1]);
        }
        __syncthreads();
    }

    int gid = lane >> 2, tig = lane & 3;
    #pragma unroll
    for (int mi = 0; mi < 4; mi++) {
        #pragma unroll
        for (int h = 0; h < 2; h++) {
            int rl = wm + mi * 16 + gid + h * 8;
            int gm = m0 + rl;
            bool valid = (gm < NROWS);
            int tgt = valid ? targets[gm + BATCH] : -1;
            float s = 0.0f;
            #pragma unroll
            for (int ni = 0; ni < 4; ni++) {
                #pragma unroll
                for (int r = 0; r < 2; r++) {
                    int col = n0 + wn + ni * 8 + tig * 2 + r;
                    float logit = acc[mi][ni][h * 2 + r] + bout[col];
                    s += __expf(logit);
                    if (valid && col == tgt) g_rowtgt[gm] = logit;
                }
            }
            s += __shfl_xor_sync(0xffffffffu, s, 1);
            s += __shfl_xor_sync(0xffffffffu, s, 2);
            if (tig == 0) atomicAdd(&sred[rl], s);
        }
    }
    __syncthreads();
    if (tid < 128 && (m0 + tid) < NROWS)
        atomicAdd(&g_rowsum[m0 + tid], sred[tid]);
}

// ---------------- final loss reduction ---------------------------------------
__global__ void loss_reduce_kernel(float* __restrict__ out)
{
    __shared__ float sbuf[256];
    int tid = threadIdx.x;
    float s = 0.0f;
    for (int r = tid; r < NROWS; r += 256)
        s += logf(g_rowsum[r]) - g_rowtgt[r];
    sbuf[tid] = s;
    __syncthreads();
    for (int o = 128; o > 0; o >>= 1) {
        if (tid < o) sbuf[tid] += sbuf[tid + o];
        __syncthreads();
    }
    if (tid == 0) out[0] = sbuf[0] / (float)BATCH;
}

// ---------------- launch -----------------------------------------------------
extern "C" void kernel_launch(void* const* d_in, const int* in_sizes, int n_in,
                              void* d_out, int out_size)
{
    (void)in_sizes; (void)n_in; (void)out_size;
    const int*   input_lines  = (const int*)  d_in[0];
    const int*   target_lines = (const int*)  d_in[1];
    const float* emb_in       = (const float*)d_in[2];
    const float* emb_tgt      = (const float*)d_in[3];
    const float* W_ih_e       = (const float*)d_in[4];
    const float* W_hh_e       = (const float*)d_in[5];
    const float* b_ih_e       = (const float*)d_in[6];
    const float* b_hh_e       = (const float*)d_in[7];
    const float* W_ih_d       = (const float*)d_in[8];
    const float* W_hh_d       = (const float*)d_in[9];
    const float* b_ih_d       = (const float*)d_in[10];
    const float* b_hh_d       = (const float*)d_in[11];
    const float* W_out        = (const float*)d_in[12];
    const float* b_out        = (const float*)d_in[13];
    float* out = (float*)d_out;

    const int SMEM_BYTES = (2 * 512 * WP + 3 * 128 * HP + 16 * HP) * 4;
    cudaFuncSetAttribute(lstm_persist,
                         cudaFuncAttributeMaxDynamicSharedMemorySize,
                         SMEM_BYTES);

    init_kernel<<<(NROWS + 255) / 256, 256>>>();

    embed_gemm128<<<dim3(G4 / 128, 24), 256>>>(
        input_lines, emb_in, W_ih_e, b_ih_e, b_hh_e, 1, SRC_LEN * BATCH);
    embed_gemm128<<<dim3(G4 / 128, 24), 256>>>(
        target_lines, emb_tgt, W_ih_d, b_ih_d, b_hh_d, 0, DSTEPS * BATCH);

    // persist at in-call launch index 3 (conv_w moved after it) so the
    // profiler's fixed capture index lands on it next round
    lstm_persist<<<NB, 256, SMEM_BYTES>>>(W_hh_e, W_hh_d, input_lines);

    conv_w_kernel<<<(VOCAB * HID / 4 + 255) / 256, 256>>>(W_out);

    proj_tc_kernel<<<dim3(VOCAB / 128, NROWS_PAD / 128), 256>>>(
        b_out, target_lines);

    loss_reduce_kernel<<<1, 256>>>(out);
}